// round 6
// baseline (speedup 1.0000x reference)
#include <cuda_runtime.h>
#include <cuda_bf16.h>
#include <cstdint>

#define N_NODES 50000
#define N_EDGES 600000
#define DIM     128
#define LN_EPS  1e-5f
#define N_TILES ((N_NODES + 127) / 128)   // 391

// ---------------------------------------------------------------------------
// Scratch (device globals: allocation-free per harness rules)
// ---------------------------------------------------------------------------
__device__ float g_agg[N_NODES * DIM];
__device__ float g_featN[N_NODES * DIM];      // feat * outnorm
__device__ int   g_degin_i[N_NODES];
__device__ int   g_degout_i[N_NODES];
__device__ float g_innorm[N_NODES];
__device__ float g_outnorm[N_NODES];
__device__ int   g_off[N_NODES + 1];
__device__ int   g_cursor[N_NODES];
__device__ int   g_ssrc[N_EDGES];
// B tiles (bf16, plain [n][k] layout): [h0_hi | h0_lo | h1_hi | h1_lo]
__device__ __align__(16) uint8_t g_Bt[4 * 32768];

// ---------------------------------------------------------------------------
__global__ void hist_kernel(const int* __restrict__ src, const int* __restrict__ dst) {
    int e = blockIdx.x * blockDim.x + threadIdx.x;
    if (e < N_EDGES) {
        atomicAdd(&g_degout_i[src[e]], 1);
        atomicAdd(&g_degin_i[dst[e]], 1);
    }
}

__global__ void norm_kernel() {
    int i = blockIdx.x * blockDim.x + threadIdx.x;
    if (i < N_NODES) {
        g_outnorm[i] = rsqrtf(fmaxf((float)g_degout_i[i], 1.0f));
        g_innorm[i]  = rsqrtf(fmaxf((float)g_degin_i[i], 1.0f));
    }
}

// featN = feat * outnorm (row-scaled source features)
__global__ __launch_bounds__(256) void scale_feat_kernel(const float* __restrict__ feat) {
    int idx = blockIdx.x * blockDim.x + threadIdx.x;   // over N_NODES*32 float4s
    if (idx < N_NODES * 32) {
        int node = idx >> 5;
        float s = g_outnorm[node];
        float4 v = reinterpret_cast<const float4*>(feat)[idx];
        v.x *= s; v.y *= s; v.z *= s; v.w *= s;
        reinterpret_cast<float4*>(g_featN)[idx] = v;
    }
}

// ---------------------------------------------------------------------------
// Exclusive prefix scan of degin (one block, 1024 threads)
// ---------------------------------------------------------------------------
__global__ __launch_bounds__(1024) void scan_kernel() {
    __shared__ int part[1024];
    const int t = threadIdx.x;
    const int CH = (N_NODES + 1023) / 1024;   // 49
    const int beg = t * CH;
    int s = 0;
#pragma unroll 4
    for (int i = 0; i < CH; i++) {
        int idx = beg + i;
        if (idx < N_NODES) s += g_degin_i[idx];
    }
    part[t] = s;
    __syncthreads();
    for (int off = 1; off < 1024; off <<= 1) {
        int v = (t >= off) ? part[t - off] : 0;
        __syncthreads();
        if (t >= off) part[t] += v;
        __syncthreads();
    }
    int run = (t == 0) ? 0 : part[t - 1];
    for (int i = 0; i < CH; i++) {
        int idx = beg + i;
        if (idx < N_NODES) {
            g_off[idx] = run;
            g_cursor[idx] = run;
            run += g_degin_i[idx];
        }
    }
    if (t == 1023) g_off[N_NODES] = run;
}

__global__ void scatter_kernel(const int* __restrict__ src, const int* __restrict__ dst) {
    int e = blockIdx.x * blockDim.x + threadIdx.x;
    if (e < N_EDGES) {
        int pos = atomicAdd(&g_cursor[dst[e]], 1);
        g_ssrc[pos] = src[e];
    }
}

// ---------------------------------------------------------------------------
// CSR aggregation: one warp per node, 4 gathers in flight per iteration.
// agg[n] = sum_{e in bucket(n)} featN[src_e]
// ---------------------------------------------------------------------------
__global__ __launch_bounds__(256) void agg_kernel() {
    const int warp = (blockIdx.x * blockDim.x + threadIdx.x) >> 5;
    const int lane = threadIdx.x & 31;
    if (warp >= N_NODES) return;
    const int beg = g_off[warp];
    const int end = g_off[warp + 1];
    const float4* fN = reinterpret_cast<const float4*>(g_featN);

    float4 a0 = make_float4(0.f, 0.f, 0.f, 0.f);
    float4 a1 = make_float4(0.f, 0.f, 0.f, 0.f);
    float4 a2 = make_float4(0.f, 0.f, 0.f, 0.f);
    float4 a3 = make_float4(0.f, 0.f, 0.f, 0.f);

    int e = beg;
    for (; e + 4 <= end; e += 4) {
        // scalar broadcast loads of 4 indices (independent)
        int s0 = g_ssrc[e], s1 = g_ssrc[e + 1], s2 = g_ssrc[e + 2], s3 = g_ssrc[e + 3];
        float4 v0 = fN[(size_t)s0 * 32 + lane];
        float4 v1 = fN[(size_t)s1 * 32 + lane];
        float4 v2 = fN[(size_t)s2 * 32 + lane];
        float4 v3 = fN[(size_t)s3 * 32 + lane];
        a0.x += v0.x; a0.y += v0.y; a0.z += v0.z; a0.w += v0.w;
        a1.x += v1.x; a1.y += v1.y; a1.z += v1.z; a1.w += v1.w;
        a2.x += v2.x; a2.y += v2.y; a2.z += v2.z; a2.w += v2.w;
        a3.x += v3.x; a3.y += v3.y; a3.z += v3.z; a3.w += v3.w;
    }
    for (; e < end; e++) {
        int s0 = g_ssrc[e];
        float4 v0 = fN[(size_t)s0 * 32 + lane];
        a0.x += v0.x; a0.y += v0.y; a0.z += v0.z; a0.w += v0.w;
    }
    a0.x += a1.x + a2.x + a3.x;
    a0.y += a1.y + a2.y + a3.y;
    a0.z += a1.z + a2.z + a3.z;
    a0.w += a1.w + a2.w + a3.w;
    reinterpret_cast<float4*>(g_agg)[(size_t)warp * 32 + lane] = a0;
}

// ---------------------------------------------------------------------------
// bf16 hi/lo split
// ---------------------------------------------------------------------------
__device__ __forceinline__ void split_bf16(float x, uint16_t& hi, uint16_t& lo) {
    __nv_bfloat16 h = __float2bfloat16(x);
    hi = __bfloat16_as_ushort(h);
    float hf = __uint_as_float((uint32_t)hi << 16);
    lo = __bfloat16_as_ushort(__float2bfloat16(x - hf));
}

// ---------------------------------------------------------------------------
// Prep: W[k][n] (fc_w half0, res_w half1) -> Bt[n][k] bf16 hi/lo tiles
// ---------------------------------------------------------------------------
__global__ void prep_b_kernel(const float* __restrict__ fc_w,
                              const float* __restrict__ res_w) {
    int id = blockIdx.x * blockDim.x + threadIdx.x;   // 0..4095
    int h  = id >> 11;
    int rem = id & 2047;
    int n  = rem >> 4;
    int kb = (rem & 15) * 8;
    const float* W = h ? res_w : fc_w;
    uint32_t hp[4], lp[4];
#pragma unroll
    for (int j = 0; j < 4; j++) {
        uint16_t h0, l0, h1, l1;
        split_bf16(W[(kb + 2 * j)     * DIM + n], h0, l0);
        split_bf16(W[(kb + 2 * j + 1) * DIM + n], h1, l1);
        hp[j] = ((uint32_t)h1 << 16) | h0;
        lp[j] = ((uint32_t)l1 << 16) | l0;
    }
    uint32_t off = (uint32_t)(n * 256 + kb * 2);
    *reinterpret_cast<uint4*>(&g_Bt[(uint32_t)(h * 2)     * 32768u + off]) =
        make_uint4(hp[0], hp[1], hp[2], hp[3]);
    *reinterpret_cast<uint4*>(&g_Bt[(uint32_t)(h * 2 + 1) * 32768u + off]) =
        make_uint4(lp[0], lp[1], lp[2], lp[3]);
}

// ---------------------------------------------------------------------------
// Persistent mma.sync bf16 GEMM + bias + LayerNorm + ReLU
// (3-term split Ah*Bh + Ah*Bl + Al*Bh, fp32 accum). B resident across tiles.
// ---------------------------------------------------------------------------
#define ROW_BYTES 272
#define TILE_BYTES (128 * ROW_BYTES)
#define SMEM_B     0
#define SMEM_A_HI  (4 * TILE_BYTES)
#define SMEM_A_LO  (SMEM_A_HI + TILE_BYTES)
#define SMEM_STATS (SMEM_A_LO + TILE_BYTES)
#define SMEM_TOTAL (SMEM_STATS + 2048)

__device__ __forceinline__ uint32_t smem_u32(const void* p) {
    uint32_t a;
    asm("{ .reg .u64 t; cvta.to.shared.u64 t, %1; cvt.u32.u64 %0, t; }"
        : "=r"(a) : "l"(p));
    return a;
}
__device__ __forceinline__ void ldsm4(uint32_t (&r)[4], uint32_t addr) {
    asm volatile("ldmatrix.sync.aligned.m8n8.x4.shared.b16 {%0,%1,%2,%3}, [%4];"
                 : "=r"(r[0]), "=r"(r[1]), "=r"(r[2]), "=r"(r[3]) : "r"(addr));
}
__device__ __forceinline__ void mma16816(float (&d)[4], const uint32_t (&a)[4],
                                         uint32_t b0, uint32_t b1) {
    asm volatile("mma.sync.aligned.m16n8k16.row.col.f32.bf16.bf16.f32 "
                 "{%0,%1,%2,%3}, {%4,%5,%6,%7}, {%8,%9}, {%0,%1,%2,%3};"
                 : "+f"(d[0]), "+f"(d[1]), "+f"(d[2]), "+f"(d[3])
                 : "r"(a[0]), "r"(a[1]), "r"(a[2]), "r"(a[3]), "r"(b0), "r"(b1));
}

__global__ __launch_bounds__(256) void gemm_mma_kernel(
    const float* __restrict__ feat,
    const float* __restrict__ fc_b,
    const float* __restrict__ ln_g,
    const float* __restrict__ ln_b,
    float* __restrict__ out)
{
    extern __shared__ __align__(16) char smem[];
    const uint32_t sb = smem_u32(smem);
    const int tid  = threadIdx.x;
    const int wid  = tid >> 5;
    const int lane = tid & 31;
    const int wm   = wid & 3;
    const int wn   = wid >> 2;

    // ---- copy B tiles into padded SMEM layout (once per CTA) ----
    {
        const uint4* src = reinterpret_cast<const uint4*>(g_Bt);
#pragma unroll
        for (int i = 0; i < 32; i++) {
            int idx = tid + i * 256;
            int t = idx >> 11, rem = idx & 2047;
            int n = rem >> 4, c = rem & 15;
            uint4 v = src[t * 2048 + n * 16 + c];
            *reinterpret_cast<uint4*>(smem + SMEM_B + t * TILE_BYTES + n * ROW_BYTES + c * 16) = v;
        }
    }

    const uint32_t lane_off = (uint32_t)((lane & 15) * ROW_BYTES + (lane >> 4) * 16);
    const int r = lane >> 2, q = lane & 3;

    for (int tile = blockIdx.x; tile < N_TILES; tile += gridDim.x) {
        const int bm0 = tile * 128;
        __syncthreads();   // B ready (first iter); prior tile fully done (later iters)

        auto load_a_half = [&](int half) {
            const float* Ap = half ? feat : g_agg;
            const int r0 = tid >> 4;
            const int kb = (tid & 15) * 8;
#pragma unroll
            for (int pass = 0; pass < 8; pass++) {
                int row_l = pass * 16 + r0;
                int row_g = bm0 + row_l;
                float x[8];
                if (row_g < N_NODES) {
                    float4 v0 = *reinterpret_cast<const float4*>(Ap + (size_t)row_g * DIM + kb);
                    float4 v1 = *reinterpret_cast<const float4*>(Ap + (size_t)row_g * DIM + kb + 4);
                    x[0]=v0.x; x[1]=v0.y; x[2]=v0.z; x[3]=v0.w;
                    x[4]=v1.x; x[5]=v1.y; x[6]=v1.z; x[7]=v1.w;
                    if (half == 0) {
                        float s = g_innorm[row_g];
#pragma unroll
                        for (int j = 0; j < 8; j++) x[j] *= s;
                    }
                } else {
#pragma unroll
                    for (int j = 0; j < 8; j++) x[j] = 0.0f;
                }
                uint32_t hp[4], lp[4];
#pragma unroll
                for (int j = 0; j < 4; j++) {
                    uint16_t h0, l0, h1, l1;
                    split_bf16(x[2 * j], h0, l0);
                    split_bf16(x[2 * j + 1], h1, l1);
                    hp[j] = ((uint32_t)h1 << 16) | h0;
                    lp[j] = ((uint32_t)l1 << 16) | l0;
                }
                uint32_t off = (uint32_t)(row_l * ROW_BYTES + kb * 2);
                *reinterpret_cast<uint4*>(smem + SMEM_A_HI + off) = make_uint4(hp[0], hp[1], hp[2], hp[3]);
                *reinterpret_cast<uint4*>(smem + SMEM_A_LO + off) = make_uint4(lp[0], lp[1], lp[2], lp[3]);
            }
        };

        float acc[2][8][4];
#pragma unroll
        for (int m = 0; m < 2; m++)
#pragma unroll
            for (int n = 0; n < 8; n++)
#pragma unroll
                for (int c = 0; c < 4; c++) acc[m][n][c] = 0.0f;

        auto compute_half = [&](int half) {
            const uint32_t bhi = sb + SMEM_B + (uint32_t)(half * 2) * TILE_BYTES;
            const uint32_t blo = bhi + TILE_BYTES;
            const uint32_t ahi = sb + SMEM_A_HI + (uint32_t)(wm * 32) * ROW_BYTES;
            const uint32_t alo = sb + SMEM_A_LO + (uint32_t)(wm * 32) * ROW_BYTES;
#pragma unroll 2
            for (int ks = 0; ks < 8; ks++) {
                const uint32_t koff = (uint32_t)(ks * 32) + lane_off;
                uint32_t ah[2][4], al[2][4];
                ldsm4(ah[0], ahi + koff);
                ldsm4(ah[1], ahi + 16 * ROW_BYTES + koff);
                ldsm4(al[0], alo + koff);
                ldsm4(al[1], alo + 16 * ROW_BYTES + koff);
#pragma unroll
                for (int ng = 0; ng < 4; ng++) {
                    uint32_t bh[4], bl[4];
                    const uint32_t nrow = (uint32_t)((wn * 64 + ng * 16) * ROW_BYTES);
                    ldsm4(bh, bhi + nrow + koff);
                    ldsm4(bl, blo + nrow + koff);
#pragma unroll
                    for (int m = 0; m < 2; m++) {
                        mma16816(acc[m][2 * ng],     ah[m], bh[0], bh[2]);
                        mma16816(acc[m][2 * ng + 1], ah[m], bh[1], bh[3]);
                        mma16816(acc[m][2 * ng],     ah[m], bl[0], bl[2]);
                        mma16816(acc[m][2 * ng + 1], ah[m], bl[1], bl[3]);
                        mma16816(acc[m][2 * ng],     al[m], bh[0], bh[2]);
                        mma16816(acc[m][2 * ng + 1], al[m], bh[1], bh[3]);
                    }
                }
            }
        };

        load_a_half(0);
        __syncthreads();
        compute_half(0);
        __syncthreads();
        load_a_half(1);
        __syncthreads();
        compute_half(1);

        // ---- epilogue: bias*in_norm, LN stats, ReLU ----
        int rowl[4];
        float innm[4];
#pragma unroll
        for (int mf = 0; mf < 2; mf++)
#pragma unroll
            for (int s = 0; s < 2; s++) {
                int i = mf * 2 + s;
                rowl[i] = wm * 32 + mf * 16 + s * 8 + r;
                int row_g = bm0 + rowl[i];
                innm[i] = (row_g < N_NODES) ? g_innorm[row_g] : 0.0f;
            }

        float s1[4] = {0.f, 0.f, 0.f, 0.f}, s2[4] = {0.f, 0.f, 0.f, 0.f};
#pragma unroll
        for (int nf = 0; nf < 8; nf++) {
            int col = wn * 64 + nf * 8 + q * 2;
            float2 bs = *reinterpret_cast<const float2*>(fc_b + col);
#pragma unroll
            for (int mf = 0; mf < 2; mf++)
#pragma unroll
                for (int s = 0; s < 2; s++) {
                    int i = mf * 2 + s;
                    float x = acc[mf][nf][s * 2]     + innm[i] * bs.x;
                    float y = acc[mf][nf][s * 2 + 1] + innm[i] * bs.y;
                    acc[mf][nf][s * 2] = x;
                    acc[mf][nf][s * 2 + 1] = y;
                    s1[i] += x + y;
                    s2[i] += x * x + y * y;
                }
        }
#pragma unroll
        for (int o = 1; o <= 2; o <<= 1)
#pragma unroll
            for (int i = 0; i < 4; i++) {
                s1[i] += __shfl_xor_sync(0xFFFFFFFFu, s1[i], o);
                s2[i] += __shfl_xor_sync(0xFFFFFFFFu, s2[i], o);
            }

        float2* stats = reinterpret_cast<float2*>(smem + SMEM_STATS);
        if (q == 0) {
#pragma unroll
            for (int i = 0; i < 4; i++)
                stats[rowl[i] * 2 + wn] = make_float2(s1[i], s2[i]);
        }
        __syncthreads();

        float mu[4], inv[4];
#pragma unroll
        for (int i = 0; i < 4; i++) {
            float2 A0 = stats[rowl[i] * 2];
            float2 A1 = stats[rowl[i] * 2 + 1];
            float S = A0.x + A1.x, S2 = A0.y + A1.y;
            mu[i] = S * (1.0f / DIM);
            float var = S2 * (1.0f / DIM) - mu[i] * mu[i];
            inv[i] = rsqrtf(var + LN_EPS);
        }

#pragma unroll
        for (int nf = 0; nf < 8; nf++) {
            int col = wn * 64 + nf * 8 + q * 2;
            float2 g2 = *reinterpret_cast<const float2*>(ln_g + col);
            float2 b2 = *reinterpret_cast<const float2*>(ln_b + col);
#pragma unroll
            for (int mf = 0; mf < 2; mf++)
#pragma unroll
                for (int s = 0; s < 2; s++) {
                    int i = mf * 2 + s;
                    int row_g = bm0 + rowl[i];
                    if (row_g < N_NODES) {
                        float2 o;
                        o.x = fmaxf((acc[mf][nf][s * 2]     - mu[i]) * inv[i] * g2.x + b2.x, 0.f);
                        o.y = fmaxf((acc[mf][nf][s * 2 + 1] - mu[i]) * inv[i] * g2.y + b2.y, 0.f);
                        *reinterpret_cast<float2*>(out + (size_t)row_g * DIM + col) = o;
                    }
                }
        }
    }
}

// ---------------------------------------------------------------------------
extern "C" void kernel_launch(void* const* d_in, const int* in_sizes, int n_in,
                              void* d_out, int out_size) {
    const float* feat  = (const float*)d_in[0];
    const int*   src   = (const int*)d_in[1];
    const int*   dst   = (const int*)d_in[2];
    const float* fc_w  = (const float*)d_in[3];
    const float* fc_b  = (const float*)d_in[4];
    const float* res_w = (const float*)d_in[5];
    const float* ln_g  = (const float*)d_in[6];
    const float* ln_b  = (const float*)d_in[7];
    float* out = (float*)d_out;

    void *din_p, *dout_p;
    cudaGetSymbolAddress(&din_p, g_degin_i);
    cudaGetSymbolAddress(&dout_p, g_degout_i);
    cudaMemsetAsync(din_p, 0, sizeof(int) * N_NODES);
    cudaMemsetAsync(dout_p, 0, sizeof(int) * N_NODES);

    hist_kernel<<<(N_EDGES + 255) / 256, 256>>>(src, dst);
    scan_kernel<<<1, 1024>>>();
    norm_kernel<<<(N_NODES + 255) / 256, 256>>>();
    scale_feat_kernel<<<(N_NODES * 32 + 255) / 256, 256>>>(feat);
    scatter_kernel<<<(N_EDGES + 255) / 256, 256>>>(src, dst);
    prep_b_kernel<<<16, 256>>>(fc_w, res_w);
    agg_kernel<<<(N_NODES * 32 + 255) / 256, 256>>>();

    cudaFuncSetAttribute(gemm_mma_kernel,
                         cudaFuncAttributeMaxDynamicSharedMemorySize, SMEM_TOTAL);
    gemm_mma_kernel<<<148, 256, SMEM_TOTAL>>>(feat, fc_b, ln_g, ln_b, out);
}

// round 7
// speedup vs baseline: 1.4309x; 1.4309x over previous
#include <cuda_runtime.h>
#include <cuda_bf16.h>
#include <cstdint>

#define N_NODES 50000
#define N_EDGES 600000
#define DIM     128
#define LN_EPS  1e-5f

// ---------------------------------------------------------------------------
// Scratch (device globals: allocation-free per harness rules)
// ---------------------------------------------------------------------------
__device__ float g_agg[N_NODES * DIM];
__device__ float g_degout[N_NODES];
__device__ float g_degin[N_NODES];
__device__ float g_outnorm[N_NODES];
__device__ float g_innorm[N_NODES];
// B tiles (bf16, plain [n][k] layout): [h0_hi | h0_lo | h1_hi | h1_lo]
__device__ __align__(16) uint8_t g_Bt[4 * 32768];

// ---------------------------------------------------------------------------
// Degree counting: one thread per edge, float atomic counts (exact < 2^24)
// ---------------------------------------------------------------------------
__global__ void deg_kernel(const int* __restrict__ src, const int* __restrict__ dst) {
    int e = blockIdx.x * blockDim.x + threadIdx.x;
    if (e < N_EDGES) {
        atomicAdd(&g_degout[src[e]], 1.0f);
        atomicAdd(&g_degin[dst[e]], 1.0f);
    }
}

// ---------------------------------------------------------------------------
// bf16 hi/lo split helpers
// ---------------------------------------------------------------------------
__device__ __forceinline__ void split_bf16(float x, uint16_t& hi, uint16_t& lo) {
    __nv_bfloat16 h = __float2bfloat16(x);
    hi = __bfloat16_as_ushort(h);
    float hf = __uint_as_float((uint32_t)hi << 16);
    lo = __bfloat16_as_ushort(__float2bfloat16(x - hf));
}

// Vectorized pair split: hi2/lo2 packed (x0 in low half, x1 in high half)
__device__ __forceinline__ void split2(float x0, float x1, uint32_t& hi2, uint32_t& lo2) {
    __nv_bfloat162 h = __floats2bfloat162_rn(x0, x1);
    hi2 = *reinterpret_cast<uint32_t*>(&h);
    float hf0 = __uint_as_float(hi2 << 16);
    float hf1 = __uint_as_float(hi2 & 0xFFFF0000u);
    __nv_bfloat162 l = __floats2bfloat162_rn(x0 - hf0, x1 - hf1);
    lo2 = *reinterpret_cast<uint32_t*>(&l);
}

// ---------------------------------------------------------------------------
// norm = rsqrt(max(deg,1)); blocks with global id < 4096 also prep B tiles:
// W[k][n] (fc_w half0, res_w half1) -> Bt[n][k] bf16 hi/lo (plain layout)
// ---------------------------------------------------------------------------
__global__ void norm_prep_kernel(const float* __restrict__ fc_w,
                                 const float* __restrict__ res_w) {
    int i = blockIdx.x * blockDim.x + threadIdx.x;
    if (i < N_NODES) {
        g_outnorm[i] = rsqrtf(fmaxf(g_degout[i], 1.0f));
        g_innorm[i]  = rsqrtf(fmaxf(g_degin[i], 1.0f));
    }
    if (i < 4096) {
        int h  = i >> 11;
        int rem = i & 2047;
        int n  = rem >> 4;
        int kb = (rem & 15) * 8;
        const float* W = h ? res_w : fc_w;
        uint32_t hp[4], lp[4];
#pragma unroll
        for (int j = 0; j < 4; j++) {
            uint16_t h0, l0, h1, l1;
            split_bf16(W[(kb + 2 * j)     * DIM + n], h0, l0);
            split_bf16(W[(kb + 2 * j + 1) * DIM + n], h1, l1);
            hp[j] = ((uint32_t)h1 << 16) | h0;
            lp[j] = ((uint32_t)l1 << 16) | l0;
        }
        uint32_t off = (uint32_t)(n * 256 + kb * 2);
        *reinterpret_cast<uint4*>(&g_Bt[(uint32_t)(h * 2)     * 32768u + off]) =
            make_uint4(hp[0], hp[1], hp[2], hp[3]);
        *reinterpret_cast<uint4*>(&g_Bt[(uint32_t)(h * 2 + 1) * 32768u + off]) =
            make_uint4(lp[0], lp[1], lp[2], lp[3]);
    }
}

// ---------------------------------------------------------------------------
// Edge aggregation: one warp per edge, red.global.add.v4.f32 (L2-resident)
// ---------------------------------------------------------------------------
__global__ void edge_kernel(const int* __restrict__ src, const int* __restrict__ dst,
                            const float* __restrict__ feat) {
    int t = blockIdx.x * blockDim.x + threadIdx.x;
    int e = t >> 5;
    int lane = t & 31;
    if (e < N_EDGES) {
        int s = src[e];
        int d = dst[e];
        float sc = g_outnorm[s];
        float4 v = reinterpret_cast<const float4*>(feat)[s * (DIM / 4) + lane];
        v.x *= sc; v.y *= sc; v.z *= sc; v.w *= sc;
        float* p = &g_agg[d * DIM + lane * 4];
        asm volatile("red.global.add.v4.f32 [%0], {%1, %2, %3, %4};"
                     :: "l"(p), "f"(v.x), "f"(v.y), "f"(v.z), "f"(v.w)
                     : "memory");
    }
}

// ---------------------------------------------------------------------------
// mma.sync bf16 GEMM + bias + LayerNorm + ReLU (3-term split, fp32 accum)
// Virtual A = [agg*in_norm | feat] (M=50000, K=256), B^T tiles precomputed.
// 256 threads = 8 warps (wm 0..3 x wn 0..1): warp tile 32 rows x 64 cols.
// ---------------------------------------------------------------------------
#define ROW_BYTES 272
#define TILE_BYTES (128 * ROW_BYTES)
#define SMEM_B     0
#define SMEM_A_HI  (4 * TILE_BYTES)
#define SMEM_A_LO  (SMEM_A_HI + TILE_BYTES)
#define SMEM_STATS (SMEM_A_LO + TILE_BYTES)
#define SMEM_TOTAL (SMEM_STATS + 2048)

__device__ __forceinline__ uint32_t smem_u32(const void* p) {
    uint32_t a;
    asm("{ .reg .u64 t; cvta.to.shared.u64 t, %1; cvt.u32.u64 %0, t; }"
        : "=r"(a) : "l"(p));
    return a;
}
__device__ __forceinline__ void ldsm4(uint32_t (&r)[4], uint32_t addr) {
    asm volatile("ldmatrix.sync.aligned.m8n8.x4.shared.b16 {%0,%1,%2,%3}, [%4];"
                 : "=r"(r[0]), "=r"(r[1]), "=r"(r[2]), "=r"(r[3]) : "r"(addr));
}
__device__ __forceinline__ void mma16816(float (&d)[4], const uint32_t (&a)[4],
                                         uint32_t b0, uint32_t b1) {
    asm volatile("mma.sync.aligned.m16n8k16.row.col.f32.bf16.bf16.f32 "
                 "{%0,%1,%2,%3}, {%4,%5,%6,%7}, {%8,%9}, {%0,%1,%2,%3};"
                 : "+f"(d[0]), "+f"(d[1]), "+f"(d[2]), "+f"(d[3])
                 : "r"(a[0]), "r"(a[1]), "r"(a[2]), "r"(a[3]), "r"(b0), "r"(b1));
}

__global__ __launch_bounds__(256) void gemm_mma_kernel(
    const float* __restrict__ feat,
    const float* __restrict__ fc_b,
    const float* __restrict__ ln_g,
    const float* __restrict__ ln_b,
    float* __restrict__ out)
{
    extern __shared__ __align__(16) char smem[];
    const uint32_t sb = smem_u32(smem);
    const int tid  = threadIdx.x;
    const int wid  = tid >> 5;
    const int lane = tid & 31;
    const int wm   = wid & 3;
    const int wn   = wid >> 2;
    const int bm0  = blockIdx.x * 128;

    // ---- copy B tiles into padded SMEM layout (128KB from L2) ----
    {
        const uint4* src = reinterpret_cast<const uint4*>(g_Bt);
#pragma unroll
        for (int i = 0; i < 32; i++) {
            int idx = tid + i * 256;
            int t = idx >> 11, rem = idx & 2047;
            int n = rem >> 4, c = rem & 15;
            uint4 v = src[t * 2048 + n * 16 + c];
            *reinterpret_cast<uint4*>(smem + SMEM_B + t * TILE_BYTES + n * ROW_BYTES + c * 16) = v;
        }
    }

    auto load_a_half = [&](int half) {
        const float* Ap = half ? feat : g_agg;
        const int r0 = tid >> 4;
        const int kb = (tid & 15) * 8;
#pragma unroll
        for (int pass = 0; pass < 8; pass++) {
            int row_l = pass * 16 + r0;
            int row_g = bm0 + row_l;
            float x[8];
            if (row_g < N_NODES) {
                float4 v0 = *reinterpret_cast<const float4*>(Ap + (size_t)row_g * DIM + kb);
                float4 v1 = *reinterpret_cast<const float4*>(Ap + (size_t)row_g * DIM + kb + 4);
                x[0]=v0.x; x[1]=v0.y; x[2]=v0.z; x[3]=v0.w;
                x[4]=v1.x; x[5]=v1.y; x[6]=v1.z; x[7]=v1.w;
                if (half == 0) {
                    float s = g_innorm[row_g];
#pragma unroll
                    for (int j = 0; j < 8; j++) x[j] *= s;
                }
            } else {
#pragma unroll
                for (int j = 0; j < 8; j++) x[j] = 0.0f;
            }
            uint32_t hp[4], lp[4];
#pragma unroll
            for (int j = 0; j < 4; j++)
                split2(x[2 * j], x[2 * j + 1], hp[j], lp[j]);
            uint32_t off = (uint32_t)(row_l * ROW_BYTES + kb * 2);
            *reinterpret_cast<uint4*>(smem + SMEM_A_HI + off) = make_uint4(hp[0], hp[1], hp[2], hp[3]);
            *reinterpret_cast<uint4*>(smem + SMEM_A_LO + off) = make_uint4(lp[0], lp[1], lp[2], lp[3]);
        }
    };

    float acc[2][8][4];
#pragma unroll
    for (int m = 0; m < 2; m++)
#pragma unroll
        for (int n = 0; n < 8; n++)
#pragma unroll
            for (int c = 0; c < 4; c++) acc[m][n][c] = 0.0f;

    const uint32_t lane_off = (uint32_t)((lane & 15) * ROW_BYTES + (lane >> 4) * 16);

    auto compute_half = [&](int half) {
        const uint32_t bhi = sb + SMEM_B + (uint32_t)(half * 2) * TILE_BYTES;
        const uint32_t blo = bhi + TILE_BYTES;
        const uint32_t ahi = sb + SMEM_A_HI + (uint32_t)(wm * 32) * ROW_BYTES;
        const uint32_t alo = sb + SMEM_A_LO + (uint32_t)(wm * 32) * ROW_BYTES;
#pragma unroll 2
        for (int ks = 0; ks < 8; ks++) {
            const uint32_t koff = (uint32_t)(ks * 32) + lane_off;
            uint32_t ah[2][4], al[2][4];
            ldsm4(ah[0], ahi + koff);
            ldsm4(ah[1], ahi + 16 * ROW_BYTES + koff);
            ldsm4(al[0], alo + koff);
            ldsm4(al[1], alo + 16 * ROW_BYTES + koff);
#pragma unroll
            for (int ng = 0; ng < 4; ng++) {
                uint32_t bh[4], bl[4];
                const uint32_t nrow = (uint32_t)((wn * 64 + ng * 16) * ROW_BYTES);
                ldsm4(bh, bhi + nrow + koff);
                ldsm4(bl, blo + nrow + koff);
#pragma unroll
                for (int m = 0; m < 2; m++) {
                    mma16816(acc[m][2 * ng],     ah[m], bh[0], bh[2]);
                    mma16816(acc[m][2 * ng + 1], ah[m], bh[1], bh[3]);
                    mma16816(acc[m][2 * ng],     ah[m], bl[0], bl[2]);
                    mma16816(acc[m][2 * ng + 1], ah[m], bl[1], bl[3]);
                    mma16816(acc[m][2 * ng],     al[m], bh[0], bh[2]);
                    mma16816(acc[m][2 * ng + 1], al[m], bh[1], bh[3]);
                }
            }
        }
    };

    load_a_half(0);
    __syncthreads();
    compute_half(0);
    __syncthreads();
    load_a_half(1);
    __syncthreads();
    compute_half(1);

    // ---- epilogue: bias*in_norm, LN stats, ReLU ----
    const int r = lane >> 2, q = lane & 3;
    int rowl[4];
    float innm[4];
#pragma unroll
    for (int mf = 0; mf < 2; mf++)
#pragma unroll
        for (int s = 0; s < 2; s++) {
            int i = mf * 2 + s;
            rowl[i] = wm * 32 + mf * 16 + s * 8 + r;
            int row_g = bm0 + rowl[i];
            innm[i] = (row_g < N_NODES) ? g_innorm[row_g] : 0.0f;
        }

    float s1[4] = {0.f, 0.f, 0.f, 0.f}, s2[4] = {0.f, 0.f, 0.f, 0.f};
#pragma unroll
    for (int nf = 0; nf < 8; nf++) {
        int col = wn * 64 + nf * 8 + q * 2;
        float2 bs = *reinterpret_cast<const float2*>(fc_b + col);
#pragma unroll
        for (int mf = 0; mf < 2; mf++)
#pragma unroll
            for (int s = 0; s < 2; s++) {
                int i = mf * 2 + s;
                float x = acc[mf][nf][s * 2]     + innm[i] * bs.x;
                float y = acc[mf][nf][s * 2 + 1] + innm[i] * bs.y;
                acc[mf][nf][s * 2] = x;
                acc[mf][nf][s * 2 + 1] = y;
                s1[i] += x + y;
                s2[i] += x * x + y * y;
            }
    }
#pragma unroll
    for (int o = 1; o <= 2; o <<= 1)
#pragma unroll
        for (int i = 0; i < 4; i++) {
            s1[i] += __shfl_xor_sync(0xFFFFFFFFu, s1[i], o);
            s2[i] += __shfl_xor_sync(0xFFFFFFFFu, s2[i], o);
        }

    float2* stats = reinterpret_cast<float2*>(smem + SMEM_STATS);
    if (q == 0) {
#pragma unroll
        for (int i = 0; i < 4; i++)
            stats[rowl[i] * 2 + wn] = make_float2(s1[i], s2[i]);
    }
    __syncthreads();

    float mu[4], inv[4];
#pragma unroll
    for (int i = 0; i < 4; i++) {
        float2 a0 = stats[rowl[i] * 2];
        float2 a1 = stats[rowl[i] * 2 + 1];
        float S = a0.x + a1.x, S2 = a0.y + a1.y;
        mu[i] = S * (1.0f / DIM);
        float var = S2 * (1.0f / DIM) - mu[i] * mu[i];
        inv[i] = rsqrtf(var + LN_EPS);
    }

#pragma unroll
    for (int nf = 0; nf < 8; nf++) {
        int col = wn * 64 + nf * 8 + q * 2;
        float2 g2 = *reinterpret_cast<const float2*>(ln_g + col);
        float2 b2 = *reinterpret_cast<const float2*>(ln_b + col);
#pragma unroll
        for (int mf = 0; mf < 2; mf++)
#pragma unroll
            for (int s = 0; s < 2; s++) {
                int i = mf * 2 + s;
                int row_g = bm0 + rowl[i];
                if (row_g < N_NODES) {
                    float2 o;
                    o.x = fmaxf((acc[mf][nf][s * 2]     - mu[i]) * inv[i] * g2.x + b2.x, 0.f);
                    o.y = fmaxf((acc[mf][nf][s * 2 + 1] - mu[i]) * inv[i] * g2.y + b2.y, 0.f);
                    *reinterpret_cast<float2*>(out + (size_t)row_g * DIM + col) = o;
                }
            }
    }
}

// ---------------------------------------------------------------------------
extern "C" void kernel_launch(void* const* d_in, const int* in_sizes, int n_in,
                              void* d_out, int out_size) {
    const float* feat  = (const float*)d_in[0];
    const int*   src   = (const int*)d_in[1];
    const int*   dst   = (const int*)d_in[2];
    const float* fc_w  = (const float*)d_in[3];
    const float* fc_b  = (const float*)d_in[4];
    const float* res_w = (const float*)d_in[5];
    const float* ln_g  = (const float*)d_in[6];
    const float* ln_b  = (const float*)d_in[7];
    float* out = (float*)d_out;

    void *agg_p, *dout_p, *din_p;
    cudaGetSymbolAddress(&agg_p, g_agg);
    cudaGetSymbolAddress(&dout_p, g_degout);
    cudaGetSymbolAddress(&din_p, g_degin);
    cudaMemsetAsync(agg_p, 0, sizeof(float) * N_NODES * DIM);
    cudaMemsetAsync(dout_p, 0, sizeof(float) * N_NODES);
    cudaMemsetAsync(din_p, 0, sizeof(float) * N_NODES);

    // kernel launch order chosen so gemm is the 4th kernel (profiled by ncu)
    deg_kernel<<<(N_EDGES + 255) / 256, 256>>>(src, dst);
    norm_prep_kernel<<<(N_NODES + 255) / 256, 256>>>(fc_w, res_w);
    edge_kernel<<<(N_EDGES * 32) / 256, 256>>>(src, dst, feat);

    cudaFuncSetAttribute(gemm_mma_kernel,
                         cudaFuncAttributeMaxDynamicSharedMemorySize, SMEM_TOTAL);
    gemm_mma_kernel<<<(N_NODES + 127) / 128, 256, SMEM_TOTAL>>>(feat, fc_b, ln_g, ln_b, out);
}

// round 8
// speedup vs baseline: 1.4601x; 1.0204x over previous
#include <cuda_runtime.h>
#include <cuda_bf16.h>
#include <cstdint>

#define N_NODES 50000
#define N_EDGES 600000
#define DIM     128
#define LN_EPS  1e-5f
#define N_TILES ((N_NODES + 127) / 128)   // 391

// ---------------------------------------------------------------------------
// Scratch (device globals: allocation-free per harness rules)
// ---------------------------------------------------------------------------
__device__ float g_agg[N_NODES * DIM];
__device__ float g_degout[N_NODES];
__device__ float g_degin[N_NODES];
__device__ float g_outnorm[N_NODES];
__device__ float g_innorm[N_NODES];
// B tiles (bf16, plain [n][k] layout): [h0_hi | h0_lo | h1_hi | h1_lo]
__device__ __align__(16) uint8_t g_Bt[4 * 32768];

// ---------------------------------------------------------------------------
__global__ void deg_kernel(const int* __restrict__ src, const int* __restrict__ dst) {
    int e = blockIdx.x * blockDim.x + threadIdx.x;
    if (e < N_EDGES) {
        atomicAdd(&g_degout[src[e]], 1.0f);
        atomicAdd(&g_degin[dst[e]], 1.0f);
    }
}

// ---------------------------------------------------------------------------
// bf16 hi/lo split helpers
// ---------------------------------------------------------------------------
__device__ __forceinline__ void split_bf16(float x, uint16_t& hi, uint16_t& lo) {
    __nv_bfloat16 h = __float2bfloat16(x);
    hi = __bfloat16_as_ushort(h);
    float hf = __uint_as_float((uint32_t)hi << 16);
    lo = __bfloat16_as_ushort(__float2bfloat16(x - hf));
}
__device__ __forceinline__ void split2(float x0, float x1, uint32_t& hi2, uint32_t& lo2) {
    __nv_bfloat162 h = __floats2bfloat162_rn(x0, x1);
    hi2 = *reinterpret_cast<uint32_t*>(&h);
    float hf0 = __uint_as_float(hi2 << 16);
    float hf1 = __uint_as_float(hi2 & 0xFFFF0000u);
    __nv_bfloat162 l = __floats2bfloat162_rn(x0 - hf0, x1 - hf1);
    lo2 = *reinterpret_cast<uint32_t*>(&l);
}

// ---------------------------------------------------------------------------
// norm + B prep fused
// ---------------------------------------------------------------------------
__global__ void norm_prep_kernel(const float* __restrict__ fc_w,
                                 const float* __restrict__ res_w) {
    int i = blockIdx.x * blockDim.x + threadIdx.x;
    if (i < N_NODES) {
        g_outnorm[i] = rsqrtf(fmaxf(g_degout[i], 1.0f));
        g_innorm[i]  = rsqrtf(fmaxf(g_degin[i], 1.0f));
    }
    if (i < 4096) {
        int h  = i >> 11;
        int rem = i & 2047;
        int n  = rem >> 4;
        int kb = (rem & 15) * 8;
        const float* W = h ? res_w : fc_w;
        uint32_t hp[4], lp[4];
#pragma unroll
        for (int j = 0; j < 4; j++) {
            uint16_t h0, l0, h1, l1;
            split_bf16(W[(kb + 2 * j)     * DIM + n], h0, l0);
            split_bf16(W[(kb + 2 * j + 1) * DIM + n], h1, l1);
            hp[j] = ((uint32_t)h1 << 16) | h0;
            lp[j] = ((uint32_t)l1 << 16) | l0;
        }
        uint32_t off = (uint32_t)(n * 256 + kb * 2);
        *reinterpret_cast<uint4*>(&g_Bt[(uint32_t)(h * 2)     * 32768u + off]) =
            make_uint4(hp[0], hp[1], hp[2], hp[3]);
        *reinterpret_cast<uint4*>(&g_Bt[(uint32_t)(h * 2 + 1) * 32768u + off]) =
            make_uint4(lp[0], lp[1], lp[2], lp[3]);
    }
}

// ---------------------------------------------------------------------------
// Edge aggregation: one warp per edge, red.global.add.v4.f32 (L2-resident)
// ---------------------------------------------------------------------------
__global__ void edge_kernel(const int* __restrict__ src, const int* __restrict__ dst,
                            const float* __restrict__ feat) {
    int t = blockIdx.x * blockDim.x + threadIdx.x;
    int e = t >> 5;
    int lane = t & 31;
    if (e < N_EDGES) {
        int s = src[e];
        int d = dst[e];
        float sc = g_outnorm[s];
        float4 v = reinterpret_cast<const float4*>(feat)[s * (DIM / 4) + lane];
        v.x *= sc; v.y *= sc; v.z *= sc; v.w *= sc;
        float* p = &g_agg[d * DIM + lane * 4];
        asm volatile("red.global.add.v4.f32 [%0], {%1, %2, %3, %4};"
                     :: "l"(p), "f"(v.x), "f"(v.y), "f"(v.z), "f"(v.w)
                     : "memory");
    }
}

// ---------------------------------------------------------------------------
// Persistent mma.sync bf16 GEMM + bias + LayerNorm + ReLU.
// 512 threads = 16 warps (wm 0..3 x wn 0..3), warp tile 32 rows x 32 cols.
// 3-term split Ah*Bh + Ah*Bl + Al*Bh, fp32 accum.
// ---------------------------------------------------------------------------
#define ROW_BYTES 272
#define TILE_BYTES (128 * ROW_BYTES)
#define SMEM_B     0
#define SMEM_A_HI  (4 * TILE_BYTES)
#define SMEM_A_LO  (SMEM_A_HI + TILE_BYTES)
#define SMEM_STATS (SMEM_A_LO + TILE_BYTES)   // 128 rows x 4 wn x float2 = 4KB
#define SMEM_TOTAL (SMEM_STATS + 4096)

__device__ __forceinline__ uint32_t smem_u32(const void* p) {
    uint32_t a;
    asm("{ .reg .u64 t; cvta.to.shared.u64 t, %1; cvt.u32.u64 %0, t; }"
        : "=r"(a) : "l"(p));
    return a;
}
__device__ __forceinline__ void ldsm4(uint32_t (&r)[4], uint32_t addr) {
    asm volatile("ldmatrix.sync.aligned.m8n8.x4.shared.b16 {%0,%1,%2,%3}, [%4];"
                 : "=r"(r[0]), "=r"(r[1]), "=r"(r[2]), "=r"(r[3]) : "r"(addr));
}
__device__ __forceinline__ void mma16816(float (&d)[4], const uint32_t (&a)[4],
                                         uint32_t b0, uint32_t b1) {
    asm volatile("mma.sync.aligned.m16n8k16.row.col.f32.bf16.bf16.f32 "
                 "{%0,%1,%2,%3}, {%4,%5,%6,%7}, {%8,%9}, {%0,%1,%2,%3};"
                 : "+f"(d[0]), "+f"(d[1]), "+f"(d[2]), "+f"(d[3])
                 : "r"(a[0]), "r"(a[1]), "r"(a[2]), "r"(a[3]), "r"(b0), "r"(b1));
}

__global__ __launch_bounds__(512) void gemm_mma_kernel(
    const float* __restrict__ feat,
    const float* __restrict__ fc_b,
    const float* __restrict__ ln_g,
    const float* __restrict__ ln_b,
    float* __restrict__ out)
{
    extern __shared__ __align__(16) char smem[];
    const uint32_t sb = smem_u32(smem);
    const int tid  = threadIdx.x;
    const int wid  = tid >> 5;
    const int lane = tid & 31;
    const int wm   = wid & 3;        // 32-row group
    const int wn   = wid >> 2;       // 32-col group

    // ---- copy B tiles into padded SMEM layout (once per CTA) ----
    {
        const uint4* src = reinterpret_cast<const uint4*>(g_Bt);
#pragma unroll
        for (int i = 0; i < 16; i++) {
            int idx = tid + i * 512;
            int t = idx >> 11, rem = idx & 2047;
            int n = rem >> 4, c = rem & 15;
            uint4 v = src[t * 2048 + n * 16 + c];
            *reinterpret_cast<uint4*>(smem + SMEM_B + t * TILE_BYTES + n * ROW_BYTES + c * 16) = v;
        }
    }

    const uint32_t lane_off = (uint32_t)((lane & 15) * ROW_BYTES + (lane >> 4) * 16);
    const int r = lane >> 2, q = lane & 3;
    float2* stats = reinterpret_cast<float2*>(smem + SMEM_STATS);

    for (int tile = blockIdx.x; tile < N_TILES; tile += gridDim.x) {
        const int bm0 = tile * 128;
        __syncthreads();   // B ready / previous tile finished

        auto load_a_half = [&](int half) {
            const float* Ap = half ? feat : g_agg;
            const int r0 = tid >> 4;            // 32 rows per pass
            const int kb = (tid & 15) * 8;
#pragma unroll
            for (int pass = 0; pass < 4; pass++) {
                int row_l = pass * 32 + r0;
                int row_g = bm0 + row_l;
                float x[8];
                if (row_g < N_NODES) {
                    float4 v0 = *reinterpret_cast<const float4*>(Ap + (size_t)row_g * DIM + kb);
                    float4 v1 = *reinterpret_cast<const float4*>(Ap + (size_t)row_g * DIM + kb + 4);
                    x[0]=v0.x; x[1]=v0.y; x[2]=v0.z; x[3]=v0.w;
                    x[4]=v1.x; x[5]=v1.y; x[6]=v1.z; x[7]=v1.w;
                    if (half == 0) {
                        float s = g_innorm[row_g];
#pragma unroll
                        for (int j = 0; j < 8; j++) x[j] *= s;
                    }
                } else {
#pragma unroll
                    for (int j = 0; j < 8; j++) x[j] = 0.0f;
                }
                uint32_t hp[4], lp[4];
#pragma unroll
                for (int j = 0; j < 4; j++)
                    split2(x[2 * j], x[2 * j + 1], hp[j], lp[j]);
                uint32_t off = (uint32_t)(row_l * ROW_BYTES + kb * 2);
                *reinterpret_cast<uint4*>(smem + SMEM_A_HI + off) = make_uint4(hp[0], hp[1], hp[2], hp[3]);
                *reinterpret_cast<uint4*>(smem + SMEM_A_LO + off) = make_uint4(lp[0], lp[1], lp[2], lp[3]);
            }
        };

        float acc[2][4][4];
#pragma unroll
        for (int m = 0; m < 2; m++)
#pragma unroll
            for (int n = 0; n < 4; n++)
#pragma unroll
                for (int c = 0; c < 4; c++) acc[m][n][c] = 0.0f;

        auto compute_half = [&](int half) {
            const uint32_t bhi = sb + SMEM_B + (uint32_t)(half * 2) * TILE_BYTES
                               + (uint32_t)(wn * 32) * ROW_BYTES;
            const uint32_t blo = bhi + TILE_BYTES;
            const uint32_t ahi = sb + SMEM_A_HI + (uint32_t)(wm * 32) * ROW_BYTES;
            const uint32_t alo = sb + SMEM_A_LO + (uint32_t)(wm * 32) * ROW_BYTES;
#pragma unroll 2
            for (int ks = 0; ks < 8; ks++) {
                const uint32_t koff = (uint32_t)(ks * 32) + lane_off;
                uint32_t ah[2][4], al[2][4];
                ldsm4(ah[0], ahi + koff);
                ldsm4(ah[1], ahi + 16 * ROW_BYTES + koff);
                ldsm4(al[0], alo + koff);
                ldsm4(al[1], alo + 16 * ROW_BYTES + koff);
#pragma unroll
                for (int ng = 0; ng < 2; ng++) {
                    uint32_t bh[4], bl[4];
                    const uint32_t nrow = (uint32_t)((ng * 16) * ROW_BYTES);
                    ldsm4(bh, bhi + nrow + koff);
                    ldsm4(bl, blo + nrow + koff);
#pragma unroll
                    for (int m = 0; m < 2; m++) {
                        mma16816(acc[m][2 * ng],     ah[m], bh[0], bh[2]);
                        mma16816(acc[m][2 * ng + 1], ah[m], bh[1], bh[3]);
                        mma16816(acc[m][2 * ng],     ah[m], bl[0], bl[2]);
                        mma16816(acc[m][2 * ng + 1], ah[m], bl[1], bl[3]);
                        mma16816(acc[m][2 * ng],     al[m], bh[0], bh[2]);
                        mma16816(acc[m][2 * ng + 1], al[m], bh[1], bh[3]);
                    }
                }
            }
        };

        load_a_half(0);
        __syncthreads();
        compute_half(0);
        __syncthreads();
        load_a_half(1);
        __syncthreads();
        compute_half(1);

        // ---- epilogue: bias*in_norm, LN stats, ReLU ----
        int rowl[4];
        float innm[4];
#pragma unroll
        for (int mf = 0; mf < 2; mf++)
#pragma unroll
            for (int s = 0; s < 2; s++) {
                int i = mf * 2 + s;
                rowl[i] = wm * 32 + mf * 16 + s * 8 + r;
                int row_g = bm0 + rowl[i];
                innm[i] = (row_g < N_NODES) ? g_innorm[row_g] : 0.0f;
            }

        float s1[4] = {0.f, 0.f, 0.f, 0.f}, s2[4] = {0.f, 0.f, 0.f, 0.f};
#pragma unroll
        for (int nf = 0; nf < 4; nf++) {
            int col = wn * 32 + nf * 8 + q * 2;
            float2 bs = *reinterpret_cast<const float2*>(fc_b + col);
#pragma unroll
            for (int mf = 0; mf < 2; mf++)
#pragma unroll
                for (int s = 0; s < 2; s++) {
                    int i = mf * 2 + s;
                    float x = acc[mf][nf][s * 2]     + innm[i] * bs.x;
                    float y = acc[mf][nf][s * 2 + 1] + innm[i] * bs.y;
                    acc[mf][nf][s * 2] = x;
                    acc[mf][nf][s * 2 + 1] = y;
                    s1[i] += x + y;
                    s2[i] += x * x + y * y;
                }
        }
#pragma unroll
        for (int o = 1; o <= 2; o <<= 1)
#pragma unroll
            for (int i = 0; i < 4; i++) {
                s1[i] += __shfl_xor_sync(0xFFFFFFFFu, s1[i], o);
                s2[i] += __shfl_xor_sync(0xFFFFFFFFu, s2[i], o);
            }

        if (q == 0) {
#pragma unroll
            for (int i = 0; i < 4; i++)
                stats[rowl[i] * 4 + wn] = make_float2(s1[i], s2[i]);
        }
        __syncthreads();

        float mu[4], inv[4];
#pragma unroll
        for (int i = 0; i < 4; i++) {
            float2 a0 = stats[rowl[i] * 4 + 0];
            float2 a1 = stats[rowl[i] * 4 + 1];
            float2 a2 = stats[rowl[i] * 4 + 2];
            float2 a3 = stats[rowl[i] * 4 + 3];
            float S = a0.x + a1.x + a2.x + a3.x;
            float S2 = a0.y + a1.y + a2.y + a3.y;
            mu[i] = S * (1.0f / DIM);
            float var = S2 * (1.0f / DIM) - mu[i] * mu[i];
            inv[i] = rsqrtf(var + LN_EPS);
        }

#pragma unroll
        for (int nf = 0; nf < 4; nf++) {
            int col = wn * 32 + nf * 8 + q * 2;
            float2 g2 = *reinterpret_cast<const float2*>(ln_g + col);
            float2 b2 = *reinterpret_cast<const float2*>(ln_b + col);
#pragma unroll
            for (int mf = 0; mf < 2; mf++)
#pragma unroll
                for (int s = 0; s < 2; s++) {
                    int i = mf * 2 + s;
                    int row_g = bm0 + rowl[i];
                    if (row_g < N_NODES) {
                        float2 o;
                        o.x = fmaxf((acc[mf][nf][s * 2]     - mu[i]) * inv[i] * g2.x + b2.x, 0.f);
                        o.y = fmaxf((acc[mf][nf][s * 2 + 1] - mu[i]) * inv[i] * g2.y + b2.y, 0.f);
                        *reinterpret_cast<float2*>(out + (size_t)row_g * DIM + col) = o;
                    }
                }
        }
    }
}

// ---------------------------------------------------------------------------
extern "C" void kernel_launch(void* const* d_in, const int* in_sizes, int n_in,
                              void* d_out, int out_size) {
    const float* feat  = (const float*)d_in[0];
    const int*   src   = (const int*)d_in[1];
    const int*   dst   = (const int*)d_in[2];
    const float* fc_w  = (const float*)d_in[3];
    const float* fc_b  = (const float*)d_in[4];
    const float* res_w = (const float*)d_in[5];
    const float* ln_g  = (const float*)d_in[6];
    const float* ln_b  = (const float*)d_in[7];
    float* out = (float*)d_out;

    void *agg_p, *dout_p, *din_p;
    cudaGetSymbolAddress(&agg_p, g_agg);
    cudaGetSymbolAddress(&dout_p, g_degout);
    cudaGetSymbolAddress(&din_p, g_degin);
    cudaMemsetAsync(agg_p, 0, sizeof(float) * N_NODES * DIM);
    cudaMemsetAsync(dout_p, 0, sizeof(float) * N_NODES);
    cudaMemsetAsync(din_p, 0, sizeof(float) * N_NODES);

    // launch order keeps gemm as kernel #4 (the one ncu profiles)
    deg_kernel<<<(N_EDGES + 255) / 256, 256>>>(src, dst);
    norm_prep_kernel<<<(N_NODES + 255) / 256, 256>>>(fc_w, res_w);
    edge_kernel<<<(N_EDGES * 32) / 256, 256>>>(src, dst, feat);

    cudaFuncSetAttribute(gemm_mma_kernel,
                         cudaFuncAttributeMaxDynamicSharedMemorySize, SMEM_TOTAL);
    gemm_mma_kernel<<<148, 512, SMEM_TOTAL>>>(feat, fc_b, ln_g, ln_b, out);
}